// round 16
// baseline (speedup 1.0000x reference)
#include <cuda_runtime.h>
#include <cuda_fp16.h>
#include <math.h>
#include <stdint.h>

#define BATCH 8192
#define DIM 256

// GEMM tiling: CTA 128x128, 8 warps of 32x64, 2 CTAs/SM, K = 256 fp16
#define TM 128
#define TN 128
#define KC 32                         // fp16 per K stage
#define NCHUNK (DIM / KC)             // 8
#define ROWPITCH 80                   // 32 fp16 = 64B, pad to 80 (16B-aligned, conflict-free)
#define STAGE_BYTES ((TM + TN) * ROWPITCH)   // 20480
#define NSTAGES 4
#define SMEM_TOTAL (STAGE_BYTES * NSTAGES)   // 81920

#define NCTILE (BATCH / 64)           // 128 column tiles of 64 (per-warp col range)

#define CORR_SCALE 524288.0           // 2^19 fixed-point for atomic accumulators
#define LOSS_SCALE 1048576.0          // 2^20 fixed-point for the final loss sum

// Row partial: top4 (vals, idx). 32B.
struct __align__(16) RP { float4 v; int4 i; };

// Scratch (device globals: allocation-free per harness rules)
static __device__ __half g_Ah[(size_t)BATCH * DIM];   // pre-scaled by 1/T
static __device__ __half g_Bh[(size_t)BATCH * DIM];
static __device__ RP    g_rp[BATCH][NCTILE];          // 32 MB
static __device__ long long g_rowsum_fx[BATCH];       // fixed-point row sums
static __device__ long long g_colsum_fx[BATCH];       // fixed-point col sums (+hard corr)
static __device__ float g_diag[BATCH];
static __device__ float g_rowlse[BATCH];
static __device__ long long g_loss_fx;                // fixed-point final loss sum

// ---------------------------------------------------------------------------
// helpers
// ---------------------------------------------------------------------------
__device__ __forceinline__ uint32_t smem_to_u32(const void* p) {
    uint32_t a;
    asm("{ .reg .u64 t; cvta.to.shared.u64 t, %1; cvt.u32.u64 %0, t; }"
        : "=r"(a) : "l"(p));
    return a;
}
__device__ __forceinline__ void cp_async16(uint32_t smem_addr, const void* gptr) {
    asm volatile("cp.async.cg.shared.global [%0], [%1], 16;"
        :: "r"(smem_addr), "l"(gptr));
}
#define CP_COMMIT() asm volatile("cp.async.commit_group;" ::: "memory")
#define CP_WAIT2()  asm volatile("cp.async.wait_group 2;" ::: "memory")

__device__ __forceinline__ void ldsm_x4(uint32_t& r0, uint32_t& r1,
                                        uint32_t& r2, uint32_t& r3, uint32_t addr) {
    asm volatile("ldmatrix.sync.aligned.m8n8.x4.shared.b16 {%0,%1,%2,%3}, [%4];"
                 : "=r"(r0), "=r"(r1), "=r"(r2), "=r"(r3) : "r"(addr));
}
__device__ __forceinline__ void mma_f16(float* d, const uint32_t* a, const uint32_t* b) {
    asm volatile(
        "mma.sync.aligned.m16n8k16.row.col.f32.f16.f16.f32 "
        "{%0,%1,%2,%3}, {%4,%5,%6,%7}, {%8,%9}, {%0,%1,%2,%3};"
        : "+f"(d[0]), "+f"(d[1]), "+f"(d[2]), "+f"(d[3])
        : "r"(a[0]), "r"(a[1]), "r"(a[2]), "r"(a[3]), "r"(b[0]), "r"(b[1]));
}

// top-4 insert tracking (value, index), descending
__device__ __forceinline__ void top4i(float v, int i,
                                      float& v0, int& i0, float& v1, int& i1,
                                      float& v2, int& i2, float& v3, int& i3)
{
    if (v > v3) {
        if (v > v0)      { v3=v2;i3=i2; v2=v1;i2=i1; v1=v0;i1=i0; v0=v;i0=i; }
        else if (v > v1) { v3=v2;i3=i2; v2=v1;i2=i1; v1=v;i1=i; }
        else if (v > v2) { v3=v2;i3=i2; v2=v;i2=i; }
        else             { v3=v;i3=i; }
    }
}

__device__ __forceinline__ void atomic_add_fx(long long* addr, float val) {
    long long q = (long long)(val * (float)CORR_SCALE);
    atomicAdd((unsigned long long*)addr, (unsigned long long)q);
}

__device__ __forceinline__ uint32_t h2_bits(__half2 h) {
    return *reinterpret_cast<uint32_t*>(&h);
}

// ---------------------------------------------------------------------------
// K0: FUSED fp16 convert (A pre-scaled by 1/T) + exact fp32 diag + zeroing.
// One warp per row; inputs read exactly once.
// ---------------------------------------------------------------------------
__global__ __launch_bounds__(256) void convert_diag_kernel(const float* __restrict__ V,
                                                           const float* __restrict__ Tm)
{
    const int row = blockIdx.x * 8 + (threadIdx.x >> 5);
    const int lane = threadIdx.x & 31;
    const float inv_t = 1.0f / 0.07f;

    const float4* v4 = (const float4*)(V + (size_t)row * DIM) + lane * 2;
    const float4* t4 = (const float4*)(Tm + (size_t)row * DIM) + lane * 2;
    float4 a0 = v4[0], a1 = v4[1];
    float4 b0 = t4[0], b1 = t4[1];

    uint4 ua, ub;
    ua.x = h2_bits(__floats2half2_rn(a0.x * inv_t, a0.y * inv_t));
    ua.y = h2_bits(__floats2half2_rn(a0.z * inv_t, a0.w * inv_t));
    ua.z = h2_bits(__floats2half2_rn(a1.x * inv_t, a1.y * inv_t));
    ua.w = h2_bits(__floats2half2_rn(a1.z * inv_t, a1.w * inv_t));
    ub.x = h2_bits(__floats2half2_rn(b0.x, b0.y));
    ub.y = h2_bits(__floats2half2_rn(b0.z, b0.w));
    ub.z = h2_bits(__floats2half2_rn(b1.x, b1.y));
    ub.w = h2_bits(__floats2half2_rn(b1.z, b1.w));
    *((uint4*)(g_Ah + (size_t)row * DIM) + lane) = ua;
    *((uint4*)(g_Bh + (size_t)row * DIM) + lane) = ub;

    float s = a0.x * b0.x + a0.y * b0.y + a0.z * b0.z + a0.w * b0.w
            + a1.x * b1.x + a1.y * b1.y + a1.z * b1.z + a1.w * b1.w;
    #pragma unroll
    for (int d = 16; d > 0; d >>= 1) s += __shfl_xor_sync(0xFFFFFFFFu, s, d);
    if (lane == 0) {
        g_diag[row] = s * inv_t;
        g_rowsum_fx[row] = 0;
        g_colsum_fx[row] = 0;
        if (row == 0) g_loss_fx = 0;
    }
}

// ---------------------------------------------------------------------------
// K1: fp16 HMMA GEMM (K=256, KC=32), 4-stage cp.async pipeline (depth-3
// prefetch, single barrier per chunk), fused epilogue. 2 CTAs/SM.
// ---------------------------------------------------------------------------
__global__ __launch_bounds__(256, 2) void mma_gemm_kernel()
{
    extern __shared__ char smem[];
    const uint32_t smem_base = smem_to_u32(smem);
    const int tid = threadIdx.x;
    const int wid = tid >> 5;
    const int lane = tid & 31;
    const int m0 = blockIdx.y * TM;
    const int n0 = blockIdx.x * TN;

    const int wm = (wid & 3) * 32;   // warp row offset in tile
    const int wn = (wid >> 2) * 64;  // warp col offset in tile

    // Precomputed per-thread loader bases (advance by KC*2 bytes per stage).
    const int lrow = tid >> 2;            // 0..63 then +64/+128/+192 via j
    const int lq = tid & 3;
    const char* gsrc[4];
    uint32_t sdst[4];
    #pragma unroll
    for (int j = 0; j < 4; j++) {
        int row = lrow + j * 64;          // 0..255
        sdst[j] = (uint32_t)(row * ROWPITCH + lq * 16);
        if (row < TM)
            gsrc[j] = (const char*)g_Ah + ((size_t)(m0 + row) * DIM + lq * 8) * 2;
        else
            gsrc[j] = (const char*)g_Bh + ((size_t)(n0 + row - TM) * DIM + lq * 8) * 2;
    }

    auto load_stage = [&](int s) {
        const uint32_t sb = smem_base + (uint32_t)(s % NSTAGES) * STAGE_BYTES;
        const int koff = s * (KC * 2);
        #pragma unroll
        for (int j = 0; j < 4; j++)
            cp_async16(sb + sdst[j], gsrc[j] + koff);
    };

    float acc[2][8][4];
    #pragma unroll
    for (int mt = 0; mt < 2; mt++)
        #pragma unroll
        for (int nt = 0; nt < 8; nt++)
            #pragma unroll
            for (int e = 0; e < 4; e++) acc[mt][nt][e] = 0.f;

    load_stage(0); CP_COMMIT();   // group 0 = stage 0
    load_stage(1); CP_COMMIT();   // group 1 = stage 1
    load_stage(2); CP_COMMIT();   // group 2 = stage 2

    for (int s = 0; s < NCHUNK; s++) {
        // commits so far = 3 + s; wait_group 2 => groups <= s complete
        CP_WAIT2();
        __syncthreads();          // single barrier per chunk (see safety note)
        if (s + 3 < NCHUNK) load_stage(s + 3);
        CP_COMMIT();              // one group per iteration (possibly empty)

        const uint32_t sb = smem_base + (uint32_t)(s % NSTAGES) * STAGE_BYTES;
        const uint32_t Asb = sb;
        const uint32_t Bsb = sb + TM * ROWPITCH;

        #pragma unroll
        for (int ks = 0; ks < 2; ks++) {
            const int kb = ks * 32;
            uint32_t a[2][4], b[8][2];
            #pragma unroll
            for (int mt = 0; mt < 2; mt++) {
                uint32_t addr = Asb + (wm + mt * 16 + (lane & 15)) * ROWPITCH
                              + kb + (lane >> 4) * 16;
                ldsm_x4(a[mt][0], a[mt][1], a[mt][2], a[mt][3], addr);
            }
            #pragma unroll
            for (int np = 0; np < 4; np++) {
                int n = wn + np * 16 + (lane & 7) + ((lane >> 4) << 3);
                uint32_t addr = Bsb + n * ROWPITCH + kb + (((lane >> 3) & 1) << 4);
                ldsm_x4(b[np * 2][0], b[np * 2][1], b[np * 2 + 1][0], b[np * 2 + 1][1], addr);
            }
            #pragma unroll
            for (int mt = 0; mt < 2; mt++)
                #pragma unroll
                for (int nt = 0; nt < 8; nt++)
                    mma_f16(acc[mt][nt], a[mt], b[nt]);
        }
        // no trailing barrier: next iteration's leading barrier orders the
        // buffer reuse (writer waits for all warps to finish this compute)
    }

    // ======================= FUSED EPILOGUE =======================
    // logits are accumulators directly (A pre-scaled by 1/T).
    // row = m0+wm+mt*16+(lane>>2)+h*8; col = n0+wn+nt*8+(lane&3)*2+e
    const int lr = lane >> 2;
    const int lc = lane & 3;
    const int ctile = blockIdx.x * 2 + (wid >> 2);   // 64-col tile index

    float cs[16];
    #pragma unroll
    for (int c = 0; c < 16; c++) cs[c] = 0.f;

    #pragma unroll
    for (int mt = 0; mt < 2; mt++) {
        #pragma unroll
        for (int h = 0; h < 2; h++) {
            const int row = m0 + wm + mt * 16 + lr + h * 8;
            float rsum = 0.f;
            float v0 = -3e38f, v1 = -3e38f, v2 = -3e38f, v3 = -3e38f;
            int i0 = 0, i1 = 0, i2 = 0, i3 = 0;
            #pragma unroll
            for (int nt = 0; nt < 8; nt++) {
                #pragma unroll
                for (int e = 0; e < 2; e++) {
                    const int col = n0 + wn + nt * 8 + lc * 2 + e;
                    float x = acc[mt][nt][h * 2 + e];
                    float ex = __expf(x);
                    rsum += ex;
                    cs[nt * 2 + e] += ex;
                    if (col != row)
                        top4i(x, col, v0, i0, v1, i1, v2, i2, v3, i3);
                }
            }
            // reduce over lc (lane bits 0..1) — snapshot before inserting
            #pragma unroll
            for (int d = 1; d <= 2; d <<= 1) {
                rsum += __shfl_xor_sync(0xFFFFFFFFu, rsum, d);
                float ov0 = __shfl_xor_sync(0xFFFFFFFFu, v0, d);
                float ov1 = __shfl_xor_sync(0xFFFFFFFFu, v1, d);
                float ov2 = __shfl_xor_sync(0xFFFFFFFFu, v2, d);
                float ov3 = __shfl_xor_sync(0xFFFFFFFFu, v3, d);
                int   oj0 = __shfl_xor_sync(0xFFFFFFFFu, i0, d);
                int   oj1 = __shfl_xor_sync(0xFFFFFFFFu, i1, d);
                int   oj2 = __shfl_xor_sync(0xFFFFFFFFu, i2, d);
                int   oj3 = __shfl_xor_sync(0xFFFFFFFFu, i3, d);
                top4i(ov0, oj0, v0, i0, v1, i1, v2, i2, v3, i3);
                top4i(ov1, oj1, v0, i0, v1, i1, v2, i2, v3, i3);
                top4i(ov2, oj2, v0, i0, v1, i1, v2, i2, v3, i3);
                top4i(ov3, oj3, v0, i0, v1, i1, v2, i2, v3, i3);
            }
            if (lc == 0) {
                RP* p = &g_rp[row][ctile];
                p->v = make_float4(v0, v1, v2, v3);
                p->i = make_int4(i0, i1, i2, i3);
                atomic_add_fx(&g_rowsum_fx[row], rsum);
            }
        }
    }

    // column sums: reduce over lr (lane bits 2..4), then fixed-point atomics
    #pragma unroll
    for (int d = 4; d <= 16; d <<= 1) {
        #pragma unroll
        for (int c = 0; c < 16; c++)
            cs[c] += __shfl_xor_sync(0xFFFFFFFFu, cs[c], d);
    }
    if (lr == 0) {
        #pragma unroll
        for (int c = 0; c < 16; c++) {
            int col = n0 + wn + (c >> 1) * 8 + lc * 2 + (c & 1);
            atomic_add_fx(&g_colsum_fx[col], cs[c]);
        }
    }
}

// ---------------------------------------------------------------------------
// K2: per-row merge of 128 top4 partials (one warp per row) -> weighted rowLSE
// + hard-negative column corrections.
// ---------------------------------------------------------------------------
__global__ __launch_bounds__(256) void rowmerge_kernel()
{
    const int row = blockIdx.x * 8 + (threadIdx.x >> 5);
    const int lane = threadIdx.x & 31;

    float v0 = -3e38f, v1 = -3e38f, v2 = -3e38f, v3 = -3e38f;
    int i0 = 0, i1 = 0, i2 = 0, i3 = 0;
    #pragma unroll
    for (int q = 0; q < 4; q++) {
        RP p = g_rp[row][lane + q * 32];
        top4i(p.v.x, p.i.x, v0, i0, v1, i1, v2, i2, v3, i3);
        top4i(p.v.y, p.i.y, v0, i0, v1, i1, v2, i2, v3, i3);
        top4i(p.v.z, p.i.z, v0, i0, v1, i1, v2, i2, v3, i3);
        top4i(p.v.w, p.i.w, v0, i0, v1, i1, v2, i2, v3, i3);
    }
    #pragma unroll
    for (int d = 16; d > 0; d >>= 1) {
        // snapshot all four before inserting (symmetric-merge hazard)
        float ov0 = __shfl_xor_sync(0xFFFFFFFFu, v0, d);
        float ov1 = __shfl_xor_sync(0xFFFFFFFFu, v1, d);
        float ov2 = __shfl_xor_sync(0xFFFFFFFFu, v2, d);
        float ov3 = __shfl_xor_sync(0xFFFFFFFFu, v3, d);
        int   oj0 = __shfl_xor_sync(0xFFFFFFFFu, i0, d);
        int   oj1 = __shfl_xor_sync(0xFFFFFFFFu, i1, d);
        int   oj2 = __shfl_xor_sync(0xFFFFFFFFu, i2, d);
        int   oj3 = __shfl_xor_sync(0xFFFFFFFFu, i3, d);
        top4i(ov0, oj0, v0, i0, v1, i1, v2, i2, v3, i3);
        top4i(ov1, oj1, v0, i0, v1, i1, v2, i2, v3, i3);
        top4i(ov2, oj2, v0, i0, v1, i1, v2, i2, v3, i3);
        top4i(ov3, oj3, v0, i0, v1, i1, v2, i2, v3, i3);
    }
    if (lane == 0) {
        float S = (float)((double)g_rowsum_fx[row] * (1.0 / CORR_SCALE));
        float e0 = expf(v0), e1 = expf(v1), e2 = expf(v2), e3 = expf(v3);
        float w0 = expf(2.f * v0), w1 = expf(2.f * v1),
              w2 = expf(2.f * v2), w3 = expf(2.f * v3);
        float Sw = S + (w0 - e0) + (w1 - e1) + (w2 - e2) + (w3 - e3);
        g_rowlse[row] = logf(Sw);
        // column corrections for this row's 4 hard negatives
        atomicAdd((unsigned long long*)&g_colsum_fx[i0],
                  (unsigned long long)(long long)((double)(w0 - e0) * CORR_SCALE));
        atomicAdd((unsigned long long*)&g_colsum_fx[i1],
                  (unsigned long long)(long long)((double)(w1 - e1) * CORR_SCALE));
        atomicAdd((unsigned long long*)&g_colsum_fx[i2],
                  (unsigned long long)(long long)((double)(w2 - e2) * CORR_SCALE));
        atomicAdd((unsigned long long*)&g_colsum_fx[i3],
                  (unsigned long long)(long long)((double)(w3 - e3) * CORR_SCALE));
    }
}

// ---------------------------------------------------------------------------
// K3: parallel loss partial sums -> fixed-point atomic (deterministic)
// ---------------------------------------------------------------------------
__global__ __launch_bounds__(256) void finalize_partial_kernel()
{
    const int i = blockIdx.x * 256 + threadIdx.x;
    float collse = logf((float)((double)g_colsum_fx[i] * (1.0 / CORR_SCALE)));
    float term = (g_rowlse[i] - g_diag[i]) + (collse - g_diag[i]);
    #pragma unroll
    for (int d = 16; d > 0; d >>= 1) term += __shfl_xor_sync(0xFFFFFFFFu, term, d);
    if ((threadIdx.x & 31) == 0) {
        long long q = (long long)((double)term * LOSS_SCALE);
        atomicAdd((unsigned long long*)&g_loss_fx, (unsigned long long)q);
    }
}

__global__ void finalize_write_kernel(float* __restrict__ out)
{
    out[0] = (float)((double)g_loss_fx * (1.0 / LOSS_SCALE) / (2.0 * (double)BATCH));
}

extern "C" void kernel_launch(void* const* d_in, const int* in_sizes, int n_in,
                              void* d_out, int out_size)
{
    (void)in_sizes; (void)n_in; (void)out_size;
    const float* V  = (const float*)d_in[0];   // vision_embed [8192, 256]
    const float* Tm = (const float*)d_in[1];   // text_embed   [8192, 256]
    float* out = (float*)d_out;

    cudaFuncSetAttribute(mma_gemm_kernel,
                         cudaFuncAttributeMaxDynamicSharedMemorySize, SMEM_TOTAL);

    convert_diag_kernel<<<BATCH / 8, 256>>>(V, Tm);
    mma_gemm_kernel<<<dim3(BATCH / TN, BATCH / TM), 256, SMEM_TOTAL>>>();
    rowmerge_kernel<<<BATCH / 8, 256>>>();
    finalize_partial_kernel<<<BATCH / 256, 256>>>();
    finalize_write_kernel<<<1, 1>>>(out);
}

// round 17
// speedup vs baseline: 1.5625x; 1.5625x over previous
#include <cuda_runtime.h>
#include <cuda_fp16.h>
#include <math.h>
#include <stdint.h>

#define BATCH 8192
#define DIM 256

// GEMM tiling: CTA 128x128, 8 warps of 32x64, 2 CTAs/SM, K = 256 fp16
#define TM 128
#define TN 128
#define KC 32                         // fp16 per K stage
#define NCHUNK (DIM / KC)             // 8
#define ROWPITCH 80                   // 32 fp16 = 64B, pad to 80 (16B-aligned, conflict-free)
#define STAGE_BYTES ((TM + TN) * ROWPITCH)   // 20480
#define NSTAGES 3
#define SMEM_TOTAL (STAGE_BYTES * NSTAGES)   // 61440

#define NCTILE (BATCH / 64)           // 128 column tiles of 64 (per-warp col range)

#define CORR_SCALE 524288.0           // 2^19 fixed-point for atomic accumulators
#define LOSS_SCALE 1048576.0          // 2^20 fixed-point for the final loss sum

// Row partial: top4 (vals, idx). 32B.
struct __align__(16) RP { float4 v; int4 i; };

// Scratch (device globals: allocation-free per harness rules)
static __device__ __half g_Ah[(size_t)BATCH * DIM];   // pre-scaled by 1/T
static __device__ __half g_Bh[(size_t)BATCH * DIM];
static __device__ RP    g_rp[BATCH][NCTILE];          // 32 MB
static __device__ long long g_rowsum_fx[BATCH];       // fixed-point row sums
static __device__ long long g_colsum_fx[BATCH];       // fixed-point col sums (+hard corr)
static __device__ float g_diag[BATCH];
static __device__ float g_rowlse[BATCH];
static __device__ long long g_loss_fx;                // fixed-point final loss sum

// ---------------------------------------------------------------------------
// helpers
// ---------------------------------------------------------------------------
__device__ __forceinline__ uint32_t smem_to_u32(const void* p) {
    uint32_t a;
    asm("{ .reg .u64 t; cvta.to.shared.u64 t, %1; cvt.u32.u64 %0, t; }"
        : "=r"(a) : "l"(p));
    return a;
}
__device__ __forceinline__ void cp_async16(uint32_t smem_addr, const void* gptr) {
    asm volatile("cp.async.cg.shared.global [%0], [%1], 16;"
        :: "r"(smem_addr), "l"(gptr));
}
#define CP_COMMIT() asm volatile("cp.async.commit_group;" ::: "memory")
#define CP_WAIT1()  asm volatile("cp.async.wait_group 1;" ::: "memory")

__device__ __forceinline__ void ldsm_x4(uint32_t& r0, uint32_t& r1,
                                        uint32_t& r2, uint32_t& r3, uint32_t addr) {
    asm volatile("ldmatrix.sync.aligned.m8n8.x4.shared.b16 {%0,%1,%2,%3}, [%4];"
                 : "=r"(r0), "=r"(r1), "=r"(r2), "=r"(r3) : "r"(addr));
}
__device__ __forceinline__ void mma_f16(float* d, const uint32_t* a, const uint32_t* b) {
    asm volatile(
        "mma.sync.aligned.m16n8k16.row.col.f32.f16.f16.f32 "
        "{%0,%1,%2,%3}, {%4,%5,%6,%7}, {%8,%9}, {%0,%1,%2,%3};"
        : "+f"(d[0]), "+f"(d[1]), "+f"(d[2]), "+f"(d[3])
        : "r"(a[0]), "r"(a[1]), "r"(a[2]), "r"(a[3]), "r"(b[0]), "r"(b[1]));
}

// top-4 insert tracking (value, index), descending
__device__ __forceinline__ void top4i(float v, int i,
                                      float& v0, int& i0, float& v1, int& i1,
                                      float& v2, int& i2, float& v3, int& i3)
{
    if (v > v3) {
        if (v > v0)      { v3=v2;i3=i2; v2=v1;i2=i1; v1=v0;i1=i0; v0=v;i0=i; }
        else if (v > v1) { v3=v2;i3=i2; v2=v1;i2=i1; v1=v;i1=i; }
        else if (v > v2) { v3=v2;i3=i2; v2=v;i2=i; }
        else             { v3=v;i3=i; }
    }
}

__device__ __forceinline__ void atomic_add_fx(long long* addr, float val) {
    long long q = (long long)(val * (float)CORR_SCALE);
    atomicAdd((unsigned long long*)addr, (unsigned long long)q);
}

__device__ __forceinline__ uint32_t h2_bits(__half2 h) {
    return *reinterpret_cast<uint32_t*>(&h);
}

// ---------------------------------------------------------------------------
// K0: FUSED fp16 convert (A pre-scaled by 1/T) + exact fp32 diag + zeroing.
// One warp per row; inputs read exactly once.
// ---------------------------------------------------------------------------
__global__ __launch_bounds__(256) void convert_diag_kernel(const float* __restrict__ V,
                                                           const float* __restrict__ Tm)
{
    const int row = blockIdx.x * 8 + (threadIdx.x >> 5);
    const int lane = threadIdx.x & 31;
    const float inv_t = 1.0f / 0.07f;

    const float4* v4 = (const float4*)(V + (size_t)row * DIM) + lane * 2;
    const float4* t4 = (const float4*)(Tm + (size_t)row * DIM) + lane * 2;
    float4 a0 = v4[0], a1 = v4[1];
    float4 b0 = t4[0], b1 = t4[1];

    uint4 ua, ub;
    ua.x = h2_bits(__floats2half2_rn(a0.x * inv_t, a0.y * inv_t));
    ua.y = h2_bits(__floats2half2_rn(a0.z * inv_t, a0.w * inv_t));
    ua.z = h2_bits(__floats2half2_rn(a1.x * inv_t, a1.y * inv_t));
    ua.w = h2_bits(__floats2half2_rn(a1.z * inv_t, a1.w * inv_t));
    ub.x = h2_bits(__floats2half2_rn(b0.x, b0.y));
    ub.y = h2_bits(__floats2half2_rn(b0.z, b0.w));
    ub.z = h2_bits(__floats2half2_rn(b1.x, b1.y));
    ub.w = h2_bits(__floats2half2_rn(b1.z, b1.w));
    *((uint4*)(g_Ah + (size_t)row * DIM) + lane) = ua;
    *((uint4*)(g_Bh + (size_t)row * DIM) + lane) = ub;

    float s = a0.x * b0.x + a0.y * b0.y + a0.z * b0.z + a0.w * b0.w
            + a1.x * b1.x + a1.y * b1.y + a1.z * b1.z + a1.w * b1.w;
    #pragma unroll
    for (int d = 16; d > 0; d >>= 1) s += __shfl_xor_sync(0xFFFFFFFFu, s, d);
    if (lane == 0) {
        g_diag[row] = s * inv_t;
        g_rowsum_fx[row] = 0;
        g_colsum_fx[row] = 0;
        if (row == 0) g_loss_fx = 0;
    }
}

// ---------------------------------------------------------------------------
// K1: fp16 HMMA GEMM (K=256, KC=32), 3-stage cp.async pipeline, fused
// epilogue: row top4 -> g_rp, row/col sums -> fixed-point atomics.
// 128x128 CTA, 8 warps of 32x64, 2 CTAs/SM.
// ---------------------------------------------------------------------------
__global__ __launch_bounds__(256, 2) void mma_gemm_kernel()
{
    extern __shared__ char smem[];
    const uint32_t smem_base = smem_to_u32(smem);
    const int tid = threadIdx.x;
    const int wid = tid >> 5;
    const int lane = tid & 31;
    const int m0 = blockIdx.y * TM;
    const int n0 = blockIdx.x * TN;

    const int wm = (wid & 3) * 32;   // warp row offset in tile
    const int wn = (wid >> 2) * 64;  // warp col offset in tile

    const char* Ag = (const char*)g_Ah;
    const char* Bg = (const char*)g_Bh;

    // stage loader: A rows [m0,m0+128) then B rows [n0,n0+128), 16B chunks
    auto load_stage = [&](int s) {
        const uint32_t sb = smem_base + (uint32_t)(s % NSTAGES) * STAGE_BYTES;
        const int kelem = s * KC;
        #pragma unroll
        for (int j = 0; j < 4; j++) {
            int c = tid + j * 256;                 // 0..1023
            int row = c >> 2, q = c & 3;           // row 0..255, q 0..3
            if (row < TM) {
                cp_async16(sb + row * ROWPITCH + q * 16,
                           Ag + ((size_t)(m0 + row) * DIM + kelem + q * 8) * 2);
            } else {
                cp_async16(sb + row * ROWPITCH + q * 16,
                           Bg + ((size_t)(n0 + row - TM) * DIM + kelem + q * 8) * 2);
            }
        }
        CP_COMMIT();
    };

    float acc[2][8][4];
    #pragma unroll
    for (int mt = 0; mt < 2; mt++)
        #pragma unroll
        for (int nt = 0; nt < 8; nt++)
            #pragma unroll
            for (int e = 0; e < 4; e++) acc[mt][nt][e] = 0.f;

    load_stage(0);
    load_stage(1);

    for (int s = 0; s < NCHUNK; s++) {
        CP_WAIT1();
        __syncthreads();
        if (s + 2 < NCHUNK) load_stage(s + 2);

        const uint32_t sb = smem_base + (uint32_t)(s % NSTAGES) * STAGE_BYTES;
        const uint32_t Asb = sb;
        const uint32_t Bsb = sb + TM * ROWPITCH;

        #pragma unroll
        for (int ks = 0; ks < 2; ks++) {
            const int kb = ks * 32;
            uint32_t a[2][4], b[8][2];
            #pragma unroll
            for (int mt = 0; mt < 2; mt++) {
                uint32_t addr = Asb + (wm + mt * 16 + (lane & 15)) * ROWPITCH
                              + kb + (lane >> 4) * 16;
                ldsm_x4(a[mt][0], a[mt][1], a[mt][2], a[mt][3], addr);
            }
            #pragma unroll
            for (int np = 0; np < 4; np++) {
                int n = wn + np * 16 + (lane & 7) + ((lane >> 4) << 3);
                uint32_t addr = Bsb + n * ROWPITCH + kb + (((lane >> 3) & 1) << 4);
                ldsm_x4(b[np * 2][0], b[np * 2][1], b[np * 2 + 1][0], b[np * 2 + 1][1], addr);
            }
            #pragma unroll
            for (int mt = 0; mt < 2; mt++)
                #pragma unroll
                for (int nt = 0; nt < 8; nt++)
                    mma_f16(acc[mt][nt], a[mt], b[nt]);
        }
        __syncthreads();
    }

    // ======================= FUSED EPILOGUE =======================
    // logits come straight from the accumulators (A pre-scaled by 1/T).
    // row = m0+wm+mt*16+(lane>>2)+h*8; col = n0+wn+nt*8+(lane&3)*2+e;
    const int lr = lane >> 2;
    const int lc = lane & 3;
    const int ctile = blockIdx.x * 2 + (wid >> 2);   // 64-col tile index

    float cs[16];
    #pragma unroll
    for (int c = 0; c < 16; c++) cs[c] = 0.f;

    #pragma unroll
    for (int mt = 0; mt < 2; mt++) {
        #pragma unroll
        for (int h = 0; h < 2; h++) {
            const int row = m0 + wm + mt * 16 + lr + h * 8;
            float rsum = 0.f;
            float v0 = -3e38f, v1 = -3e38f, v2 = -3e38f, v3 = -3e38f;
            int i0 = 0, i1 = 0, i2 = 0, i3 = 0;
            #pragma unroll
            for (int nt = 0; nt < 8; nt++) {
                #pragma unroll
                for (int e = 0; e < 2; e++) {
                    const int col = n0 + wn + nt * 8 + lc * 2 + e;
                    float x = acc[mt][nt][h * 2 + e];
                    float ex = __expf(x);
                    rsum += ex;
                    cs[nt * 2 + e] += ex;
                    if (col != row)
                        top4i(x, col, v0, i0, v1, i1, v2, i2, v3, i3);
                }
            }
            // reduce over lc (lane bits 0..1) — snapshot before inserting
            #pragma unroll
            for (int d = 1; d <= 2; d <<= 1) {
                rsum += __shfl_xor_sync(0xFFFFFFFFu, rsum, d);
                float ov0 = __shfl_xor_sync(0xFFFFFFFFu, v0, d);
                float ov1 = __shfl_xor_sync(0xFFFFFFFFu, v1, d);
                float ov2 = __shfl_xor_sync(0xFFFFFFFFu, v2, d);
                float ov3 = __shfl_xor_sync(0xFFFFFFFFu, v3, d);
                int   oj0 = __shfl_xor_sync(0xFFFFFFFFu, i0, d);
                int   oj1 = __shfl_xor_sync(0xFFFFFFFFu, i1, d);
                int   oj2 = __shfl_xor_sync(0xFFFFFFFFu, i2, d);
                int   oj3 = __shfl_xor_sync(0xFFFFFFFFu, i3, d);
                top4i(ov0, oj0, v0, i0, v1, i1, v2, i2, v3, i3);
                top4i(ov1, oj1, v0, i0, v1, i1, v2, i2, v3, i3);
                top4i(ov2, oj2, v0, i0, v1, i1, v2, i2, v3, i3);
                top4i(ov3, oj3, v0, i0, v1, i1, v2, i2, v3, i3);
            }
            if (lc == 0) {
                RP* p = &g_rp[row][ctile];
                p->v = make_float4(v0, v1, v2, v3);
                p->i = make_int4(i0, i1, i2, i3);
                atomic_add_fx(&g_rowsum_fx[row], rsum);
            }
        }
    }

    // column sums: reduce over lr (lane bits 2..4), then fixed-point atomics
    #pragma unroll
    for (int d = 4; d <= 16; d <<= 1) {
        #pragma unroll
        for (int c = 0; c < 16; c++)
            cs[c] += __shfl_xor_sync(0xFFFFFFFFu, cs[c], d);
    }
    if (lr == 0) {
        #pragma unroll
        for (int c = 0; c < 16; c++) {
            int col = n0 + wn + (c >> 1) * 8 + lc * 2 + (c & 1);
            atomic_add_fx(&g_colsum_fx[col], cs[c]);
        }
    }
}

// ---------------------------------------------------------------------------
// K2: per-row merge of 128 top4 partials (one warp per row) -> weighted rowLSE
// + hard-negative column corrections.
// ---------------------------------------------------------------------------
__global__ __launch_bounds__(256) void rowmerge_kernel()
{
    const int row = blockIdx.x * 8 + (threadIdx.x >> 5);
    const int lane = threadIdx.x & 31;

    float v0 = -3e38f, v1 = -3e38f, v2 = -3e38f, v3 = -3e38f;
    int i0 = 0, i1 = 0, i2 = 0, i3 = 0;
    #pragma unroll
    for (int q = 0; q < 4; q++) {
        RP p = g_rp[row][lane + q * 32];
        top4i(p.v.x, p.i.x, v0, i0, v1, i1, v2, i2, v3, i3);
        top4i(p.v.y, p.i.y, v0, i0, v1, i1, v2, i2, v3, i3);
        top4i(p.v.z, p.i.z, v0, i0, v1, i1, v2, i2, v3, i3);
        top4i(p.v.w, p.i.w, v0, i0, v1, i1, v2, i2, v3, i3);
    }
    #pragma unroll
    for (int d = 16; d > 0; d >>= 1) {
        // snapshot all four before inserting (symmetric-merge hazard)
        float ov0 = __shfl_xor_sync(0xFFFFFFFFu, v0, d);
        float ov1 = __shfl_xor_sync(0xFFFFFFFFu, v1, d);
        float ov2 = __shfl_xor_sync(0xFFFFFFFFu, v2, d);
        float ov3 = __shfl_xor_sync(0xFFFFFFFFu, v3, d);
        int   oj0 = __shfl_xor_sync(0xFFFFFFFFu, i0, d);
        int   oj1 = __shfl_xor_sync(0xFFFFFFFFu, i1, d);
        int   oj2 = __shfl_xor_sync(0xFFFFFFFFu, i2, d);
        int   oj3 = __shfl_xor_sync(0xFFFFFFFFu, i3, d);
        top4i(ov0, oj0, v0, i0, v1, i1, v2, i2, v3, i3);
        top4i(ov1, oj1, v0, i0, v1, i1, v2, i2, v3, i3);
        top4i(ov2, oj2, v0, i0, v1, i1, v2, i2, v3, i3);
        top4i(ov3, oj3, v0, i0, v1, i1, v2, i2, v3, i3);
    }
    if (lane == 0) {
        float S = (float)((double)g_rowsum_fx[row] * (1.0 / CORR_SCALE));
        float e0 = expf(v0), e1 = expf(v1), e2 = expf(v2), e3 = expf(v3);
        float w0 = expf(2.f * v0), w1 = expf(2.f * v1),
              w2 = expf(2.f * v2), w3 = expf(2.f * v3);
        float Sw = S + (w0 - e0) + (w1 - e1) + (w2 - e2) + (w3 - e3);
        g_rowlse[row] = logf(Sw);
        // column corrections for this row's 4 hard negatives
        atomicAdd((unsigned long long*)&g_colsum_fx[i0],
                  (unsigned long long)(long long)((double)(w0 - e0) * CORR_SCALE));
        atomicAdd((unsigned long long*)&g_colsum_fx[i1],
                  (unsigned long long)(long long)((double)(w1 - e1) * CORR_SCALE));
        atomicAdd((unsigned long long*)&g_colsum_fx[i2],
                  (unsigned long long)(long long)((double)(w2 - e2) * CORR_SCALE));
        atomicAdd((unsigned long long*)&g_colsum_fx[i3],
                  (unsigned long long)(long long)((double)(w3 - e3) * CORR_SCALE));
    }
}

// ---------------------------------------------------------------------------
// K3: parallel loss partial sums -> fixed-point atomic (deterministic)
// ---------------------------------------------------------------------------
__global__ __launch_bounds__(256) void finalize_partial_kernel()
{
    const int i = blockIdx.x * 256 + threadIdx.x;
    float collse = logf((float)((double)g_colsum_fx[i] * (1.0 / CORR_SCALE)));
    float term = (g_rowlse[i] - g_diag[i]) + (collse - g_diag[i]);
    #pragma unroll
    for (int d = 16; d > 0; d >>= 1) term += __shfl_xor_sync(0xFFFFFFFFu, term, d);
    if ((threadIdx.x & 31) == 0) {
        long long q = (long long)((double)term * LOSS_SCALE);
        atomicAdd((unsigned long long*)&g_loss_fx, (unsigned long long)q);
    }
}

__global__ void finalize_write_kernel(float* __restrict__ out)
{
    out[0] = (float)((double)g_loss_fx * (1.0 / LOSS_SCALE) / (2.0 * (double)BATCH));
}

extern "C" void kernel_launch(void* const* d_in, const int* in_sizes, int n_in,
                              void* d_out, int out_size)
{
    (void)in_sizes; (void)n_in; (void)out_size;
    const float* V  = (const float*)d_in[0];   // vision_embed [8192, 256]
    const float* Tm = (const float*)d_in[1];   // text_embed   [8192, 256]
    float* out = (float*)d_out;

    cudaFuncSetAttribute(mma_gemm_kernel,
                         cudaFuncAttributeMaxDynamicSharedMemorySize, SMEM_TOTAL);

    convert_diag_kernel<<<BATCH / 8, 256>>>(V, Tm);
    mma_gemm_kernel<<<dim3(BATCH / TN, BATCH / TM), 256, SMEM_TOTAL>>>();
    rowmerge_kernel<<<BATCH / 8, 256>>>();
    finalize_partial_kernel<<<BATCH / 256, 256>>>();
    finalize_write_kernel<<<1, 1>>>(out);
}